// round 15
// baseline (speedup 1.0000x reference)
#include <cuda_runtime.h>
#include <cuda_fp16.h>
#include <cstdint>

#define B_    8
#define V_    4096
#define P_    32
#define CIN   64
#define COUT  128
#define BV    (B_ * V_)      // 32768
#define K2    512

__device__ __half g_ypow[(size_t)BV * K2];
__device__ __half g_W[(size_t)COUT * K2];
__device__ __half g_S16[(size_t)B_ * V_ * CIN];

__device__ __forceinline__ void mma_f16(float& d0, float& d1, float& d2, float& d3,
                                        uint32_t a0, uint32_t a1, uint32_t a2, uint32_t a3,
                                        uint32_t b0, uint32_t b1) {
    asm volatile(
        "mma.sync.aligned.m16n8k16.row.col.f32.f16.f16.f32 "
        "{%0,%1,%2,%3}, {%4,%5,%6,%7}, {%8,%9}, {%0,%1,%2,%3};"
        : "+f"(d0), "+f"(d1), "+f"(d2), "+f"(d3)
        : "r"(a0), "r"(a1), "r"(a2), "r"(a3), "r"(b0), "r"(b1));
}

__device__ __forceinline__ void ldsm_x4(uint32_t* r, uint32_t addr) {
    asm volatile("ldmatrix.sync.aligned.m8n8.x4.shared.b16 {%0,%1,%2,%3}, [%4];"
        : "=r"(r[0]), "=r"(r[1]), "=r"(r[2]), "=r"(r[3]) : "r"(addr));
}

__device__ __forceinline__ void ldsm_x4_t(uint32_t* r, uint32_t addr) {
    asm volatile("ldmatrix.sync.aligned.m8n8.x4.trans.shared.b16 {%0,%1,%2,%3}, [%4];"
        : "=r"(r[0]), "=r"(r[1]), "=r"(r[2]), "=r"(r[3]) : "r"(addr));
}

__device__ __forceinline__ float sqclip(float x) {
    return sqrtf(fmaxf(x, 1e-4f));
}

__device__ __forceinline__ uint32_t smem_u32(const void* p) {
    return (uint32_t)__cvta_generic_to_shared(p);
}

__device__ __forceinline__ void cp_async16(uint32_t dst, const void* src) {
    asm volatile("cp.async.cg.shared.global [%0], [%1], 16;" :: "r"(dst), "l"(src));
}

// XOR swizzle for tiles with 16-word (64B) rows: chunk c in 0..3
__device__ __forceinline__ int swz(int row, int c) {
    return row * 16 + ((c ^ ((row >> 1) & 3)) << 2);
}

// pack 8 floats (two float4) -> 4 half2 words
__device__ __forceinline__ uint4 pack8h(float4 v0, float4 v1) {
    __half2 h0 = __floats2half2_rn(v0.x, v0.y);
    __half2 h1 = __floats2half2_rn(v0.z, v0.w);
    __half2 h2 = __floats2half2_rn(v1.x, v1.y);
    __half2 h3 = __floats2half2_rn(v1.z, v1.w);
    uint4 u;
    u.x = *(uint32_t*)&h0; u.y = *(uint32_t*)&h1;
    u.z = *(uint32_t*)&h2; u.w = *(uint32_t*)&h3;
    return u;
}

// ---------------------------------------------------------------------------
// Prologue: signal (CTAs 0..255) and W (CTAs 256..263) fp32 -> fp16.
// ---------------------------------------------------------------------------
__global__ __launch_bounds__(256)
void cvt_kernel(const float* __restrict__ signal, const float* __restrict__ W)
{
    const int cta = blockIdx.x;
    const float4* src;
    uint2* dst;
    int base;
    if (cta < 256) {
        src = (const float4*)signal;  dst = (uint2*)g_S16;
        base = cta * 2048 + threadIdx.x;
    } else {
        src = (const float4*)W;       dst = (uint2*)g_W;
        base = (cta - 256) * 2048 + threadIdx.x;
    }
    #pragma unroll
    for (int j = 0; j < 8; ++j) {
        int i = base + j * 256;
        float4 v = src[i];
        __half2 h0 = __floats2half2_rn(v.x, v.y);
        __half2 h1 = __floats2half2_rn(v.z, v.w);
        uint2 u;
        u.x = *(uint32_t*)&h0; u.y = *(uint32_t*)&h1;
        dst[i] = u;
    }
}

// ---------------------------------------------------------------------------
// Kernel 1 (R12 structure, occupancy unlocked to 32 CTAs/SM = 64 warps):
// CTA = 64 threads = 2 warps = ONE bv, full fp16 datapath.
// D[m=rn 32][n=c'] = ck^T * S, fp16 m16n8k16 mma; warp h owns c-half h.
// S gathered via cp.async (overlaps with ck convert/stage). Bounce [c2][rn]
// half2 stride 36.  Incremental-register epilogue, r-half shuffle exchange,
// coalesced uint4 STG.
// ---------------------------------------------------------------------------
#define YB_STR 36   // bounce row stride in words (half2 units)

__global__ __launch_bounds__(64, 32)
void ypow_kernel(const int*   __restrict__ pidx,
                 const float* __restrict__ convk)
{
    __shared__ uint32_t sCK[32 * 16];     // fp16 [p][rn 32h] swizzled, 2KB
    __shared__ uint32_t sSh[2][640];      // per-warp: S tile (512w) / bounce (576w)

    const int tid  = threadIdx.x;
    const int warp = tid >> 5;      // c-half
    const int lane = tid & 31;
    const int bv   = blockIdx.x;
    const int g    = lane >> 2;
    const int tig  = lane & 3;
    const int grp  = lane >> 3;     // ldsm address group
    const int gi   = lane & 7;

    // lane p = lane: gathered signal row base (in halves)
    const int2 ip = ((const int2*)pidx)[bv * P_ + lane];
    const int base = (ip.x * V_ + ip.y) * CIN;

    // Issue S-half gather via cp.async FIRST (overlaps with ck staging below)
    {
        uint32_t* sS = sSh[warp];
        #pragma unroll
        for (int j = 0; j < 4; ++j) {
            int id = j * 32 + lane;
            int row = id >> 2, c = id & 3;
            int bp = __shfl_sync(0xffffffffu, base, row);
            cp_async16(smem_u32(&sS[swz(row, c)]),
                       g_S16 + bp + warp * 32 + c * 8);
        }
        asm volatile("cp.async.commit_group;");
    }

    // Stage ck [p][rn] -> fp16 swizzled: 128 chunks, 2 per thread
    {
        const float* ck = convk + (size_t)bv * 1024;
        #pragma unroll
        for (int it = 0; it < 2; ++it) {
            int id = tid + it * 64;
            int row = id >> 2, c = id & 3;
            const float4* src = (const float4*)(ck + row * 32 + c * 8);
            *(uint4*)&sCK[swz(row, c)] = pack8h(src[0], src[1]);
        }
    }
    asm volatile("cp.async.wait_group 0;");
    __syncthreads();   // sCK written by both warps; S tiles landed

    const uint32_t sCKb = smem_u32(sCK);
    const uint32_t sSb  = smem_u32(sSh[warp]);

    // D[m=rn 32][n = its 32 c']: 2 mt x 4 nt x 2 ks (k16 each)
    float acc[2][4][4];
    #pragma unroll
    for (int i = 0; i < 2; ++i)
        #pragma unroll
        for (int j = 0; j < 4; ++j)
            #pragma unroll
            for (int e = 0; e < 4; ++e) acc[i][j][e] = 0.0f;

    #pragma unroll
    for (int ks = 0; ks < 2; ++ks) {
        uint32_t a[2][4];
        #pragma unroll
        for (int mt = 0; mt < 2; ++mt) {
            int row = ks * 16 + (grp >> 1) * 8 + gi;
            int ch  = mt * 2 + (grp & 1);
            ldsm_x4_t(a[mt], sCKb + 4 * swz(row, ch));
        }
        uint32_t b[2][4];
        #pragma unroll
        for (int ntp = 0; ntp < 2; ++ntp) {
            int row = ks * 16 + (grp & 1) * 8 + gi;
            int ch  = ntp * 2 + (grp >> 1);
            ldsm_x4_t(b[ntp], sSb + 4 * swz(row, ch));
        }
        #pragma unroll
        for (int mt = 0; mt < 2; ++mt)
            #pragma unroll
            for (int nt = 0; nt < 4; ++nt) {
                uint32_t b0 = b[nt >> 1][(nt & 1) * 2];
                uint32_t b1 = b[nt >> 1][(nt & 1) * 2 + 1];
                mma_f16(acc[mt][nt][0], acc[mt][nt][1], acc[mt][nt][2], acc[mt][nt][3],
                        a[mt][0], a[mt][1], a[mt][2], a[mt][3], b0, b1);
            }
    }
    __syncwarp();   // done reading own sS half; overlay it with bounce

    // acc -> bounce [c2][rn] half2 (c-pair packed), 16 STS.32, conflict-free.
    uint32_t* sY = sSh[warp];
    #pragma unroll
    for (int mt = 0; mt < 2; ++mt) {
        #pragma unroll
        for (int nt = 0; nt < 4; ++nt) {
            const int c2 = nt * 4 + tig;
            const int rn = mt * 16 + g;
            __half2 h01 = __floats2half2_rn(acc[mt][nt][0], acc[mt][nt][1]);
            __half2 h23 = __floats2half2_rn(acc[mt][nt][2], acc[mt][nt][3]);
            sY[c2 * YB_STR + rn]     = *(uint32_t*)&h01;
            sY[c2 * YB_STR + rn + 8] = *(uint32_t*)&h23;
        }
    }
    __syncwarp();

    // Epilogue: lane = (c2 = lane&15, r = lane>>4).  4x LDS.128, incremental
    // square-accumulate into 8 l-buckets; sqrt; pack; r-half exchange via
    // shfl.xor(16); coalesced uint4 STG.
    {
        const uint32_t* rp = sY + (lane & 15) * YB_STR + (lane >> 4) * 16;
        float s0[4] = {0.f, 0.f, 0.f, 0.f};
        float s1[4] = {0.f, 0.f, 0.f, 0.f};
        #pragma unroll
        for (int j = 0; j < 4; ++j) {
            uint4 q = *(const uint4*)&rp[j * 4];
            uint32_t w[4] = {q.x, q.y, q.z, q.w};
            #pragma unroll
            for (int e = 0; e < 4; ++e) {
                const int n = j * 4 + e;
                const int l = (n == 0) ? 0 : (n <= 3) ? 1 : (n <= 8) ? 2 : 3;
                float2 f = __half22float2(*(const __half2*)&w[e]);
                s0[l] += f.x * f.x;
                s1[l] += f.y * f.y;
            }
        }
        __half2 u0 = __floats2half2_rn(sqclip(s0[0]), sqclip(s0[1]));
        __half2 u1 = __floats2half2_rn(sqclip(s0[2]), sqclip(s0[3]));
        __half2 u2 = __floats2half2_rn(sqclip(s1[0]), sqclip(s1[1]));
        __half2 u3 = __floats2half2_rn(sqclip(s1[2]), sqclip(s1[3]));
        uint32_t w0 = *(uint32_t*)&u0, w1 = *(uint32_t*)&u1;
        uint32_t w2 = *(uint32_t*)&u2, w3 = *(uint32_t*)&u3;
        uint32_t p0 = __shfl_xor_sync(0xffffffffu, w0, 16);
        uint32_t p1 = __shfl_xor_sync(0xffffffffu, w1, 16);
        uint32_t p2 = __shfl_xor_sync(0xffffffffu, w2, 16);
        uint32_t p3 = __shfl_xor_sync(0xffffffffu, w3, 16);
        uint4 o;
        int c;
        if (lane < 16) {
            c = 2 * (lane & 15);
            o.x = w0; o.y = w1; o.z = p0; o.w = p1;
        } else {
            c = 2 * (lane & 15) + 1;
            o.x = p2; o.y = p3; o.z = w2; o.w = w3;
        }
        ((uint4*)g_ypow)[(size_t)bv * 64 + warp * 32 + c] = o;
    }
}

// ---------------------------------------------------------------------------
// Kernel 2: out = ypow * W^T + bias, relu.  fp16 m16n8k16 mma.  CTA 256 thr,
// tile 128m x 128n, KT=32 halves, 4-stage cp.async pipeline, XOR swizzle,
// ldmatrix.x4 frags.  Warp = 32m x 64n.  (R12 version, verbatim)
// ---------------------------------------------------------------------------
#define KT     32
#define NKT    (K2 / KT)        // 16
#define M_BLK  128
#define N_BLK  128

__global__ __launch_bounds__(256, 2)
void out_gemm_kernel(const float* __restrict__ bias,
                     float* __restrict__ out)
{
    __shared__ uint32_t sA[4][M_BLK * 16];
    __shared__ uint32_t sB[4][N_BLK * 16];

    const int tid  = threadIdx.x;
    const int warp = tid >> 5;
    const int lane = tid & 31;
    const int g    = lane >> 2;
    const int tig  = lane & 3;
    const int wm   = warp >> 1;
    const int wn   = warp & 1;
    const int m0   = blockIdx.x * M_BLK;
    const int lrow = lane & 15;
    const int lch  = lane >> 4;

    const __half* yp = g_ypow;

    float acc[2][8][4];
    #pragma unroll
    for (int a = 0; a < 2; ++a)
        #pragma unroll
        for (int b = 0; b < 8; ++b)
            #pragma unroll
            for (int c = 0; c < 4; ++c) acc[a][b][c] = 0.0f;

    auto stage = [&](int kt, int st) {
        #pragma unroll
        for (int i = 0; i < 2; ++i) {
            int id = tid + i * 256;
            int row = id >> 2, c = id & 3;
            cp_async16(smem_u32(&sA[st][swz(row, c)]),
                       yp + (size_t)(m0 + row) * K2 + kt * KT + c * 8);
        }
        #pragma unroll
        for (int i = 0; i < 2; ++i) {
            int id = tid + i * 256;
            int row = id >> 2, c = id & 3;
            cp_async16(smem_u32(&sB[st][swz(row, c)]),
                       g_W + (size_t)row * K2 + kt * KT + c * 8);
        }
        asm volatile("cp.async.commit_group;");
    };

    stage(0, 0);
    stage(1, 1);
    stage(2, 2);

    for (int kt = 0; kt < NKT; ++kt) {
        asm volatile("cp.async.wait_group 2;");
        __syncthreads();
        if (kt + 3 < NKT) stage(kt + 3, (kt + 3) & 3);
        else asm volatile("cp.async.commit_group;");
        const int st = kt & 3;

        #pragma unroll
        for (int ks = 0; ks < 2; ++ks) {
            const int ch = ks * 2 + lch;
            uint32_t a[2][4];
            #pragma unroll
            for (int mi = 0; mi < 2; ++mi) {
                int row = wm * 32 + mi * 16 + lrow;
                ldsm_x4(a[mi], smem_u32(&sA[st][swz(row, ch)]));
            }
            uint32_t b[4][4];
            #pragma unroll
            for (int p = 0; p < 4; ++p) {
                int row = wn * 64 + p * 16 + lrow;
                ldsm_x4(b[p], smem_u32(&sB[st][swz(row, ch)]));
            }
            #pragma unroll
            for (int p = 0; p < 4; ++p) {
                mma_f16(acc[0][2*p][0], acc[0][2*p][1], acc[0][2*p][2], acc[0][2*p][3],
                        a[0][0], a[0][1], a[0][2], a[0][3], b[p][0], b[p][2]);
                mma_f16(acc[0][2*p+1][0], acc[0][2*p+1][1], acc[0][2*p+1][2], acc[0][2*p+1][3],
                        a[0][0], a[0][1], a[0][2], a[0][3], b[p][1], b[p][3]);
                mma_f16(acc[1][2*p][0], acc[1][2*p][1], acc[1][2*p][2], acc[1][2*p][3],
                        a[1][0], a[1][1], a[1][2], a[1][3], b[p][0], b[p][2]);
                mma_f16(acc[1][2*p+1][0], acc[1][2*p+1][1], acc[1][2*p+1][2], acc[1][2*p+1][3],
                        a[1][0], a[1][1], a[1][2], a[1][3], b[p][1], b[p][3]);
            }
        }
    }

    #pragma unroll
    for (int nt = 0; nt < 8; ++nt) {
        const int col = wn * 64 + nt * 8 + 2 * tig;
        const float b0 = __ldg(&bias[col]);
        const float b1 = __ldg(&bias[col + 1]);
        #pragma unroll
        for (int mi = 0; mi < 2; ++mi) {
            const int row = m0 + wm * 32 + mi * 16 + g;
            float2 v0, v1;
            v0.x = fmaxf(acc[mi][nt][0] + b0, 0.0f);
            v0.y = fmaxf(acc[mi][nt][1] + b1, 0.0f);
            v1.x = fmaxf(acc[mi][nt][2] + b0, 0.0f);
            v1.y = fmaxf(acc[mi][nt][3] + b1, 0.0f);
            *(float2*)(out + (size_t)row * COUT + col)       = v0;
            *(float2*)(out + (size_t)(row + 8) * COUT + col) = v1;
        }
    }
}

extern "C" void kernel_launch(void* const* d_in, const int* in_sizes, int n_in,
                              void* d_out, int out_size)
{
    const float* signal = (const float*)d_in[0];
    const int*   pidx   = (const int*)  d_in[1];
    const float* convk  = (const float*)d_in[2];
    const float* W      = (const float*)d_in[3];
    const float* bias   = (const float*)d_in[4];
    float* out = (float*)d_out;

    cvt_kernel<<<264, 256>>>(signal, W);
    ypow_kernel<<<BV, 64>>>(pidx, convk);
    out_gemm_kernel<<<BV / M_BLK, 256>>>(bias, out);
}

// round 16
// speedup vs baseline: 1.3892x; 1.3892x over previous
#include <cuda_runtime.h>
#include <cuda_fp16.h>
#include <cstdint>

#define B_    8
#define V_    4096
#define P_    32
#define CIN   64
#define COUT  128
#define BV    (B_ * V_)      // 32768
#define K2    512

__device__ __half g_ypow[(size_t)BV * K2];
__device__ __half g_W[(size_t)COUT * K2];
__device__ __half g_S16[(size_t)B_ * V_ * CIN];

__device__ __forceinline__ void mma_f16(float& d0, float& d1, float& d2, float& d3,
                                        uint32_t a0, uint32_t a1, uint32_t a2, uint32_t a3,
                                        uint32_t b0, uint32_t b1) {
    asm volatile(
        "mma.sync.aligned.m16n8k16.row.col.f32.f16.f16.f32 "
        "{%0,%1,%2,%3}, {%4,%5,%6,%7}, {%8,%9}, {%0,%1,%2,%3};"
        : "+f"(d0), "+f"(d1), "+f"(d2), "+f"(d3)
        : "r"(a0), "r"(a1), "r"(a2), "r"(a3), "r"(b0), "r"(b1));
}

__device__ __forceinline__ void ldsm_x4(uint32_t* r, uint32_t addr) {
    asm volatile("ldmatrix.sync.aligned.m8n8.x4.shared.b16 {%0,%1,%2,%3}, [%4];"
        : "=r"(r[0]), "=r"(r[1]), "=r"(r[2]), "=r"(r[3]) : "r"(addr));
}

__device__ __forceinline__ void ldsm_x4_t(uint32_t* r, uint32_t addr) {
    asm volatile("ldmatrix.sync.aligned.m8n8.x4.trans.shared.b16 {%0,%1,%2,%3}, [%4];"
        : "=r"(r[0]), "=r"(r[1]), "=r"(r[2]), "=r"(r[3]) : "r"(addr));
}

__device__ __forceinline__ float sqclip(float x) {
    return sqrtf(fmaxf(x, 1e-4f));
}

__device__ __forceinline__ uint32_t smem_u32(const void* p) {
    return (uint32_t)__cvta_generic_to_shared(p);
}

__device__ __forceinline__ void cp_async16(uint32_t dst, const void* src) {
    asm volatile("cp.async.cg.shared.global [%0], [%1], 16;" :: "r"(dst), "l"(src));
}

// XOR swizzle, 16-word (64B) rows, chunk c in 0..3
__device__ __forceinline__ int swz(int row, int c) {
    return row * 16 + ((c ^ ((row >> 1) & 3)) << 2);
}
// XOR swizzle, 32-word (128B) rows, chunk c in 0..7
__device__ __forceinline__ int swz8(int row, int c) {
    return row * 32 + ((c ^ (row & 7)) << 2);
}

__device__ __forceinline__ uint4 pack8h(float4 v0, float4 v1) {
    __half2 h0 = __floats2half2_rn(v0.x, v0.y);
    __half2 h1 = __floats2half2_rn(v0.z, v0.w);
    __half2 h2 = __floats2half2_rn(v1.x, v1.y);
    __half2 h3 = __floats2half2_rn(v1.z, v1.w);
    uint4 u;
    u.x = *(uint32_t*)&h0; u.y = *(uint32_t*)&h1;
    u.z = *(uint32_t*)&h2; u.w = *(uint32_t*)&h3;
    return u;
}

// ---------------------------------------------------------------------------
// Prologue: signal (CTAs 0..255) and W (CTAs 256..263) fp32 -> fp16.
// (R12 version, verbatim)
// ---------------------------------------------------------------------------
__global__ __launch_bounds__(256)
void cvt_kernel(const float* __restrict__ signal, const float* __restrict__ W)
{
    const int cta = blockIdx.x;
    const float4* src;
    uint2* dst;
    int base;
    if (cta < 256) {
        src = (const float4*)signal;  dst = (uint2*)g_S16;
        base = cta * 2048 + threadIdx.x;
    } else {
        src = (const float4*)W;       dst = (uint2*)g_W;
        base = (cta - 256) * 2048 + threadIdx.x;
    }
    #pragma unroll
    for (int j = 0; j < 8; ++j) {
        int i = base + j * 256;
        float4 v = src[i];
        __half2 h0 = __floats2half2_rn(v.x, v.y);
        __half2 h1 = __floats2half2_rn(v.z, v.w);
        uint2 u;
        u.x = *(uint32_t*)&h0; u.y = *(uint32_t*)&h1;
        dst[i] = u;
    }
}

// ---------------------------------------------------------------------------
// Kernel 1 (R12 version, verbatim: 16 CTAs/SM optimum).
// CTA = 64 threads = 2 warps = ONE bv, full fp16 datapath.
// ---------------------------------------------------------------------------
#define YB_STR 36   // bounce row stride in words (half2 units)

__global__ __launch_bounds__(64, 16)
void ypow_kernel(const int*   __restrict__ pidx,
                 const float* __restrict__ convk)
{
    __shared__ uint32_t sCK[32 * 16];     // fp16 [p][rn 32h] swizzled, 2KB
    __shared__ uint32_t sSh[2][640];      // per-warp: S tile (512w) / bounce (576w)

    const int tid  = threadIdx.x;
    const int warp = tid >> 5;      // c-half
    const int lane = tid & 31;
    const int bv   = blockIdx.x;
    const int g    = lane >> 2;
    const int tig  = lane & 3;
    const int grp  = lane >> 3;     // ldsm address group
    const int gi   = lane & 7;

    const int2 ip = ((const int2*)pidx)[bv * P_ + lane];
    const int base = (ip.x * V_ + ip.y) * CIN;

    // S-half gather via cp.async (overlaps with ck staging below)
    {
        uint32_t* sS = sSh[warp];
        #pragma unroll
        for (int j = 0; j < 4; ++j) {
            int id = j * 32 + lane;
            int row = id >> 2, c = id & 3;
            int bp = __shfl_sync(0xffffffffu, base, row);
            cp_async16(smem_u32(&sS[swz(row, c)]),
                       g_S16 + bp + warp * 32 + c * 8);
        }
        asm volatile("cp.async.commit_group;");
    }

    // Stage ck [p][rn] -> fp16 swizzled: 128 chunks, 2 per thread
    {
        const float* ck = convk + (size_t)bv * 1024;
        #pragma unroll
        for (int it = 0; it < 2; ++it) {
            int id = tid + it * 64;
            int row = id >> 2, c = id & 3;
            const float4* src = (const float4*)(ck + row * 32 + c * 8);
            *(uint4*)&sCK[swz(row, c)] = pack8h(src[0], src[1]);
        }
    }
    asm volatile("cp.async.wait_group 0;");
    __syncthreads();

    const uint32_t sCKb = smem_u32(sCK);
    const uint32_t sSb  = smem_u32(sSh[warp]);

    float acc[2][4][4];
    #pragma unroll
    for (int i = 0; i < 2; ++i)
        #pragma unroll
        for (int j = 0; j < 4; ++j)
            #pragma unroll
            for (int e = 0; e < 4; ++e) acc[i][j][e] = 0.0f;

    #pragma unroll
    for (int ks = 0; ks < 2; ++ks) {
        uint32_t a[2][4];
        #pragma unroll
        for (int mt = 0; mt < 2; ++mt) {
            int row = ks * 16 + (grp >> 1) * 8 + gi;
            int ch  = mt * 2 + (grp & 1);
            ldsm_x4_t(a[mt], sCKb + 4 * swz(row, ch));
        }
        uint32_t b[2][4];
        #pragma unroll
        for (int ntp = 0; ntp < 2; ++ntp) {
            int row = ks * 16 + (grp & 1) * 8 + gi;
            int ch  = ntp * 2 + (grp >> 1);
            ldsm_x4_t(b[ntp], sSb + 4 * swz(row, ch));
        }
        #pragma unroll
        for (int mt = 0; mt < 2; ++mt)
            #pragma unroll
            for (int nt = 0; nt < 4; ++nt) {
                uint32_t b0 = b[nt >> 1][(nt & 1) * 2];
                uint32_t b1 = b[nt >> 1][(nt & 1) * 2 + 1];
                mma_f16(acc[mt][nt][0], acc[mt][nt][1], acc[mt][nt][2], acc[mt][nt][3],
                        a[mt][0], a[mt][1], a[mt][2], a[mt][3], b0, b1);
            }
    }
    __syncwarp();

    uint32_t* sY = sSh[warp];
    #pragma unroll
    for (int mt = 0; mt < 2; ++mt) {
        #pragma unroll
        for (int nt = 0; nt < 4; ++nt) {
            const int c2 = nt * 4 + tig;
            const int rn = mt * 16 + g;
            __half2 h01 = __floats2half2_rn(acc[mt][nt][0], acc[mt][nt][1]);
            __half2 h23 = __floats2half2_rn(acc[mt][nt][2], acc[mt][nt][3]);
            sY[c2 * YB_STR + rn]     = *(uint32_t*)&h01;
            sY[c2 * YB_STR + rn + 8] = *(uint32_t*)&h23;
        }
    }
    __syncwarp();

    {
        const uint32_t* rp = sY + (lane & 15) * YB_STR + (lane >> 4) * 16;
        float s0[4] = {0.f, 0.f, 0.f, 0.f};
        float s1[4] = {0.f, 0.f, 0.f, 0.f};
        #pragma unroll
        for (int j = 0; j < 4; ++j) {
            uint4 q = *(const uint4*)&rp[j * 4];
            uint32_t w[4] = {q.x, q.y, q.z, q.w};
            #pragma unroll
            for (int e = 0; e < 4; ++e) {
                const int n = j * 4 + e;
                const int l = (n == 0) ? 0 : (n <= 3) ? 1 : (n <= 8) ? 2 : 3;
                float2 f = __half22float2(*(const __half2*)&w[e]);
                s0[l] += f.x * f.x;
                s1[l] += f.y * f.y;
            }
        }
        __half2 u0 = __floats2half2_rn(sqclip(s0[0]), sqclip(s0[1]));
        __half2 u1 = __floats2half2_rn(sqclip(s0[2]), sqclip(s0[3]));
        __half2 u2 = __floats2half2_rn(sqclip(s1[0]), sqclip(s1[1]));
        __half2 u3 = __floats2half2_rn(sqclip(s1[2]), sqclip(s1[3]));
        uint32_t w0 = *(uint32_t*)&u0, w1 = *(uint32_t*)&u1;
        uint32_t w2 = *(uint32_t*)&u2, w3 = *(uint32_t*)&u3;
        uint32_t p0 = __shfl_xor_sync(0xffffffffu, w0, 16);
        uint32_t p1 = __shfl_xor_sync(0xffffffffu, w1, 16);
        uint32_t p2 = __shfl_xor_sync(0xffffffffu, w2, 16);
        uint32_t p3 = __shfl_xor_sync(0xffffffffu, w3, 16);
        uint4 o;
        int c;
        if (lane < 16) {
            c = 2 * (lane & 15);
            o.x = w0; o.y = w1; o.z = p0; o.w = p1;
        } else {
            c = 2 * (lane & 15) + 1;
            o.x = p2; o.y = p3; o.z = w2; o.w = w3;
        }
        ((uint4*)g_ypow)[(size_t)bv * 64 + warp * 32 + c] = o;
    }
}

// ---------------------------------------------------------------------------
// Kernel 2: out = ypow * W^T + bias, relu.  fp16 m16n8k16 mma.  CTA 256 thr,
// tile 128m x 128n, KT=64 halves, 3-stage cp.async pipeline (8 iterations,
// half the barriers of KT=32), 128B-row XOR swizzle, ldmatrix.x4 frags.
// ---------------------------------------------------------------------------
#define KT     64
#define NKT    (K2 / KT)        // 8
#define M_BLK  128
#define N_BLK  128

__global__ __launch_bounds__(256, 2)
void out_gemm_kernel(const float* __restrict__ bias,
                     float* __restrict__ out)
{
    __shared__ uint32_t sA[3][M_BLK * 32];   // 3 x 16KB
    __shared__ uint32_t sB[3][N_BLK * 32];   // 3 x 16KB

    const int tid  = threadIdx.x;
    const int warp = tid >> 5;
    const int lane = tid & 31;
    const int g    = lane >> 2;
    const int tig  = lane & 3;
    const int wm   = warp >> 1;
    const int wn   = warp & 1;
    const int m0   = blockIdx.x * M_BLK;
    const int lrow = lane & 15;
    const int lch  = lane >> 4;

    const __half* yp = g_ypow;

    float acc[2][8][4];
    #pragma unroll
    for (int a = 0; a < 2; ++a)
        #pragma unroll
        for (int b = 0; b < 8; ++b)
            #pragma unroll
            for (int c = 0; c < 4; ++c) acc[a][b][c] = 0.0f;

    auto stage = [&](int kt, int st) {
        #pragma unroll
        for (int i = 0; i < 4; ++i) {          // A: 1024 chunks
            int id = tid + i * 256;
            int row = id >> 3, c = id & 7;
            cp_async16(smem_u32(&sA[st][swz8(row, c)]),
                       yp + (size_t)(m0 + row) * K2 + kt * KT + c * 8);
        }
        #pragma unroll
        for (int i = 0; i < 4; ++i) {          // B: 1024 chunks
            int id = tid + i * 256;
            int row = id >> 3, c = id & 7;
            cp_async16(smem_u32(&sB[st][swz8(row, c)]),
                       g_W + (size_t)row * K2 + kt * KT + c * 8);
        }
        asm volatile("cp.async.commit_group;");
    };

    stage(0, 0);
    stage(1, 1);
    stage(2, 2);

    for (int kt = 0; kt < NKT; ++kt) {
        if (kt < NKT - 2)       asm volatile("cp.async.wait_group 2;");
        else if (kt == NKT - 2) asm volatile("cp.async.wait_group 1;");
        else                    asm volatile("cp.async.wait_group 0;");
        __syncthreads();
        const int st = kt % 3;

        #pragma unroll
        for (int ks = 0; ks < 4; ++ks) {
            const int ch = ks * 2 + lch;
            uint32_t a[2][4];
            #pragma unroll
            for (int mi = 0; mi < 2; ++mi) {
                int row = wm * 32 + mi * 16 + lrow;
                ldsm_x4(a[mi], smem_u32(&sA[st][swz8(row, ch)]));
            }
            uint32_t b[4][4];
            #pragma unroll
            for (int p = 0; p < 4; ++p) {
                int row = wn * 64 + p * 16 + lrow;
                ldsm_x4(b[p], smem_u32(&sB[st][swz8(row, ch)]));
            }
            #pragma unroll
            for (int p = 0; p < 4; ++p) {
                mma_f16(acc[0][2*p][0], acc[0][2*p][1], acc[0][2*p][2], acc[0][2*p][3],
                        a[0][0], a[0][1], a[0][2], a[0][3], b[p][0], b[p][2]);
                mma_f16(acc[0][2*p+1][0], acc[0][2*p+1][1], acc[0][2*p+1][2], acc[0][2*p+1][3],
                        a[0][0], a[0][1], a[0][2], a[0][3], b[p][1], b[p][3]);
                mma_f16(acc[1][2*p][0], acc[1][2*p][1], acc[1][2*p][2], acc[1][2*p][3],
                        a[1][0], a[1][1], a[1][2], a[1][3], b[p][0], b[p][2]);
                mma_f16(acc[1][2*p+1][0], acc[1][2*p+1][1], acc[1][2*p+1][2], acc[1][2*p+1][3],
                        a[1][0], a[1][1], a[1][2], a[1][3], b[p][1], b[p][3]);
            }
        }
        __syncthreads();                      // buffer st free
        if (kt + 3 < NKT) stage(kt + 3, st);  // refill just-freed buffer
    }

    #pragma unroll
    for (int nt = 0; nt < 8; ++nt) {
        const int col = wn * 64 + nt * 8 + 2 * tig;
        const float b0 = __ldg(&bias[col]);
        const float b1 = __ldg(&bias[col + 1]);
        #pragma unroll
        for (int mi = 0; mi < 2; ++mi) {
            const int row = m0 + wm * 32 + mi * 16 + g;
            float2 v0, v1;
            v0.x = fmaxf(acc[mi][nt][0] + b0, 0.0f);
            v0.y = fmaxf(acc[mi][nt][1] + b1, 0.0f);
            v1.x = fmaxf(acc[mi][nt][2] + b0, 0.0f);
            v1.y = fmaxf(acc[mi][nt][3] + b1, 0.0f);
            *(float2*)(out + (size_t)row * COUT + col)       = v0;
            *(float2*)(out + (size_t)(row + 8) * COUT + col) = v1;
        }
    }
}

extern "C" void kernel_launch(void* const* d_in, const int* in_sizes, int n_in,
                              void* d_out, int out_size)
{
    const float* signal = (const float*)d_in[0];
    const int*   pidx   = (const int*)  d_in[1];
    const float* convk  = (const float*)d_in[2];
    const float* W      = (const float*)d_in[3];
    const float* bias   = (const float*)d_in[4];
    float* out = (float*)d_out;

    cvt_kernel<<<264, 256>>>(signal, W);
    ypow_kernel<<<BV, 64>>>(pidx, convk);
    out_gemm_kernel<<<BV / M_BLK, 256>>>(bias, out);
}

// round 17
// speedup vs baseline: 1.4326x; 1.0312x over previous
#include <cuda_runtime.h>
#include <cuda_fp16.h>
#include <cstdint>

#define B_    8
#define V_    4096
#define P_    32
#define CIN   64
#define COUT  128
#define BV    (B_ * V_)      // 32768
#define K2    512

__device__ __half g_ypow[(size_t)BV * K2];
__device__ __half g_W[(size_t)COUT * K2];
__device__ __half g_S16[(size_t)B_ * V_ * CIN];

__device__ __forceinline__ void mma_f16(float& d0, float& d1, float& d2, float& d3,
                                        uint32_t a0, uint32_t a1, uint32_t a2, uint32_t a3,
                                        uint32_t b0, uint32_t b1) {
    asm volatile(
        "mma.sync.aligned.m16n8k16.row.col.f32.f16.f16.f32 "
        "{%0,%1,%2,%3}, {%4,%5,%6,%7}, {%8,%9}, {%0,%1,%2,%3};"
        : "+f"(d0), "+f"(d1), "+f"(d2), "+f"(d3)
        : "r"(a0), "r"(a1), "r"(a2), "r"(a3), "r"(b0), "r"(b1));
}

__device__ __forceinline__ void ldsm_x4(uint32_t* r, uint32_t addr) {
    asm volatile("ldmatrix.sync.aligned.m8n8.x4.shared.b16 {%0,%1,%2,%3}, [%4];"
        : "=r"(r[0]), "=r"(r[1]), "=r"(r[2]), "=r"(r[3]) : "r"(addr));
}

__device__ __forceinline__ void ldsm_x4_t(uint32_t* r, uint32_t addr) {
    asm volatile("ldmatrix.sync.aligned.m8n8.x4.trans.shared.b16 {%0,%1,%2,%3}, [%4];"
        : "=r"(r[0]), "=r"(r[1]), "=r"(r[2]), "=r"(r[3]) : "r"(addr));
}

__device__ __forceinline__ float sqclip(float x) {
    return sqrtf(fmaxf(x, 1e-4f));
}

__device__ __forceinline__ uint32_t smem_u32(const void* p) {
    return (uint32_t)__cvta_generic_to_shared(p);
}

__device__ __forceinline__ void cp_async16(uint32_t dst, const void* src) {
    asm volatile("cp.async.cg.shared.global [%0], [%1], 16;" :: "r"(dst), "l"(src));
}

// XOR swizzle, 16-word (64B) rows, chunk c in 0..3
__device__ __forceinline__ int swz(int row, int c) {
    return row * 16 + ((c ^ ((row >> 1) & 3)) << 2);
}
// XOR swizzle, 32-word (128B) rows, chunk c in 0..7
__device__ __forceinline__ int swz8(int row, int c) {
    return row * 32 + ((c ^ (row & 7)) << 2);
}

__device__ __forceinline__ uint4 pack8h(float4 v0, float4 v1) {
    __half2 h0 = __floats2half2_rn(v0.x, v0.y);
    __half2 h1 = __floats2half2_rn(v0.z, v0.w);
    __half2 h2 = __floats2half2_rn(v1.x, v1.y);
    __half2 h3 = __floats2half2_rn(v1.z, v1.w);
    uint4 u;
    u.x = *(uint32_t*)&h0; u.y = *(uint32_t*)&h1;
    u.z = *(uint32_t*)&h2; u.w = *(uint32_t*)&h3;
    return u;
}

// ---------------------------------------------------------------------------
// Prologue: signal (CTAs 0..255) and W (CTAs 256..263) fp32 -> fp16.
// (R16 version, verbatim)
// ---------------------------------------------------------------------------
__global__ __launch_bounds__(256)
void cvt_kernel(const float* __restrict__ signal, const float* __restrict__ W)
{
    const int cta = blockIdx.x;
    const float4* src;
    uint2* dst;
    int base;
    if (cta < 256) {
        src = (const float4*)signal;  dst = (uint2*)g_S16;
        base = cta * 2048 + threadIdx.x;
    } else {
        src = (const float4*)W;       dst = (uint2*)g_W;
        base = (cta - 256) * 2048 + threadIdx.x;
    }
    #pragma unroll
    for (int j = 0; j < 8; ++j) {
        int i = base + j * 256;
        float4 v = src[i];
        __half2 h0 = __floats2half2_rn(v.x, v.y);
        __half2 h1 = __floats2half2_rn(v.z, v.w);
        uint2 u;
        u.x = *(uint32_t*)&h0; u.y = *(uint32_t*)&h1;
        dst[i] = u;
    }
}

// ---------------------------------------------------------------------------
// Kernel 1: CTA = 64 threads = 2 warps, processes 2 bv with a double buffer.
// While bv0 computes (mma + bounce + epilogue), bv1's S gather (cp.async)
// and ck LDGs are in flight.  smem 14KB -> still 16 CTAs/SM; one
// __syncthreads per bv (same as R12/R16).  Math identical to R16.
// ---------------------------------------------------------------------------
#define YB_STR 36   // bounce row stride in words (half2 units)

__global__ __launch_bounds__(64, 16)
void ypow_kernel(const int*   __restrict__ pidx,
                 const float* __restrict__ convk)
{
    __shared__ uint32_t sCK[2][512];        // fp16 [p][rn 32h] swizzled, 2x2KB
    __shared__ uint32_t sSh[2][2][640];     // [stage][warp] S tile / bounce

    const int tid  = threadIdx.x;
    const int warp = tid >> 5;      // c-half
    const int lane = tid & 31;
    const int bv0  = blockIdx.x * 2;
    const int g    = lane >> 2;
    const int tig  = lane & 3;
    const int grp  = lane >> 3;     // ldsm address group
    const int gi   = lane & 7;

    // cp.async S-half gather for bv into stage st
    auto prefetch_S = [&](int bv, int st) {
        const int2 ip = ((const int2*)pidx)[bv * P_ + lane];
        const int base = (ip.x * V_ + ip.y) * CIN;
        uint32_t* sS = sSh[st][warp];
        #pragma unroll
        for (int j = 0; j < 4; ++j) {
            int id = j * 32 + lane;
            int row = id >> 2, c = id & 3;
            int bp = __shfl_sync(0xffffffffu, base, row);
            cp_async16(smem_u32(&sS[swz(row, c)]),
                       g_S16 + bp + warp * 32 + c * 8);
        }
        asm volatile("cp.async.commit_group;");
    };

    // ck row/chunk for this thread's two staging slots
    const int ckrow0 = tid >> 2,        ckc0 = tid & 3;          // slot it=0
    const int ckrow1 = (tid + 64) >> 2, ckc1 = (tid + 64) & 3;   // slot it=1

    // ---- prologue: bv0 in flight ----
    prefetch_S(bv0, 0);
    {
        const float* ck = convk + (size_t)bv0 * 1024;
        const float4* s0 = (const float4*)(ck + ckrow0 * 32 + ckc0 * 8);
        const float4* s1 = (const float4*)(ck + ckrow1 * 32 + ckc1 * 8);
        *(uint4*)&sCK[0][swz(ckrow0, ckc0)] = pack8h(s0[0], s0[1]);
        *(uint4*)&sCK[0][swz(ckrow1, ckc1)] = pack8h(s1[0], s1[1]);
    }
    asm volatile("cp.async.wait_group 0;");
    __syncthreads();

    #pragma unroll
    for (int i = 0; i < 2; ++i) {
        const int bv = bv0 + i;

        // kick off bv1's streams before computing bv0
        float4 ckn0a, ckn0b, ckn1a, ckn1b;
        if (i == 0) {
            prefetch_S(bv0 + 1, 1);
            const float* ck = convk + (size_t)(bv0 + 1) * 1024;
            const float4* s0 = (const float4*)(ck + ckrow0 * 32 + ckc0 * 8);
            const float4* s1 = (const float4*)(ck + ckrow1 * 32 + ckc1 * 8);
            ckn0a = s0[0]; ckn0b = s0[1];
            ckn1a = s1[0]; ckn1b = s1[1];
        }

        const uint32_t sCKb = smem_u32(sCK[i]);
        const uint32_t sSb  = smem_u32(sSh[i][warp]);

        float acc[2][4][4];
        #pragma unroll
        for (int x = 0; x < 2; ++x)
            #pragma unroll
            for (int y = 0; y < 4; ++y)
                #pragma unroll
                for (int e = 0; e < 4; ++e) acc[x][y][e] = 0.0f;

        #pragma unroll
        for (int ks = 0; ks < 2; ++ks) {
            uint32_t a[2][4];
            #pragma unroll
            for (int mt = 0; mt < 2; ++mt) {
                int row = ks * 16 + (grp >> 1) * 8 + gi;
                int ch  = mt * 2 + (grp & 1);
                ldsm_x4_t(a[mt], sCKb + 4 * swz(row, ch));
            }
            uint32_t b[2][4];
            #pragma unroll
            for (int ntp = 0; ntp < 2; ++ntp) {
                int row = ks * 16 + (grp & 1) * 8 + gi;
                int ch  = ntp * 2 + (grp >> 1);
                ldsm_x4_t(b[ntp], sSb + 4 * swz(row, ch));
            }
            #pragma unroll
            for (int mt = 0; mt < 2; ++mt)
                #pragma unroll
                for (int nt = 0; nt < 4; ++nt) {
                    uint32_t b0 = b[nt >> 1][(nt & 1) * 2];
                    uint32_t b1 = b[nt >> 1][(nt & 1) * 2 + 1];
                    mma_f16(acc[mt][nt][0], acc[mt][nt][1], acc[mt][nt][2], acc[mt][nt][3],
                            a[mt][0], a[mt][1], a[mt][2], a[mt][3], b0, b1);
                }
        }
        __syncwarp();   // done reading own sS[i] half; overlay it with bounce

        // acc -> bounce [c2][rn] half2 (stride 36), conflict-free
        uint32_t* sY = sSh[i][warp];
        #pragma unroll
        for (int mt = 0; mt < 2; ++mt) {
            #pragma unroll
            for (int nt = 0; nt < 4; ++nt) {
                const int c2 = nt * 4 + tig;
                const int rn = mt * 16 + g;
                __half2 h01 = __floats2half2_rn(acc[mt][nt][0], acc[mt][nt][1]);
                __half2 h23 = __floats2half2_rn(acc[mt][nt][2], acc[mt][nt][3]);
                sY[c2 * YB_STR + rn]     = *(uint32_t*)&h01;
                sY[c2 * YB_STR + rn + 8] = *(uint32_t*)&h23;
            }
        }
        __syncwarp();

        // epilogue: incremental l-bucket accumulate + shuffle exchange + STG
        {
            const uint32_t* rp = sY + (lane & 15) * YB_STR + (lane >> 4) * 16;
            float s0[4] = {0.f, 0.f, 0.f, 0.f};
            float s1[4] = {0.f, 0.f, 0.f, 0.f};
            #pragma unroll
            for (int j = 0; j < 4; ++j) {
                uint4 q = *(const uint4*)&rp[j * 4];
                uint32_t w[4] = {q.x, q.y, q.z, q.w};
                #pragma unroll
                for (int e = 0; e < 4; ++e) {
                    const int n = j * 4 + e;
                    const int l = (n == 0) ? 0 : (n <= 3) ? 1 : (n <= 8) ? 2 : 3;
                    float2 f = __half22float2(*(const __half2*)&w[e]);
                    s0[l] += f.x * f.x;
                    s1[l] += f.y * f.y;
                }
            }
            __half2 u0 = __floats2half2_rn(sqclip(s0[0]), sqclip(s0[1]));
            __half2 u1 = __floats2half2_rn(sqclip(s0[2]), sqclip(s0[3]));
            __half2 u2 = __floats2half2_rn(sqclip(s1[0]), sqclip(s1[1]));
            __half2 u3 = __floats2half2_rn(sqclip(s1[2]), sqclip(s1[3]));
            uint32_t w0 = *(uint32_t*)&u0, w1 = *(uint32_t*)&u1;
            uint32_t w2 = *(uint32_t*)&u2, w3 = *(uint32_t*)&u3;
            uint32_t p0 = __shfl_xor_sync(0xffffffffu, w0, 16);
            uint32_t p1 = __shfl_xor_sync(0xffffffffu, w1, 16);
            uint32_t p2 = __shfl_xor_sync(0xffffffffu, w2, 16);
            uint32_t p3 = __shfl_xor_sync(0xffffffffu, w3, 16);
            uint4 o;
            int c;
            if (lane < 16) {
                c = 2 * (lane & 15);
                o.x = w0; o.y = w1; o.z = p0; o.w = p1;
            } else {
                c = 2 * (lane & 15) + 1;
                o.x = p2; o.y = p3; o.z = w2; o.w = w3;
            }
            ((uint4*)g_ypow)[(size_t)bv * 64 + warp * 32 + c] = o;
        }

        if (i == 0) {
            // pack + store bv1's ck (LDGs issued before bv0's compute)
            *(uint4*)&sCK[1][swz(ckrow0, ckc0)] = pack8h(ckn0a, ckn0b);
            *(uint4*)&sCK[1][swz(ckrow1, ckc1)] = pack8h(ckn1a, ckn1b);
            asm volatile("cp.async.wait_group 0;");
            __syncthreads();   // sCK[1] + sS[1] ready for iteration 1
        }
    }
}

// ---------------------------------------------------------------------------
// Kernel 2: out = ypow * W^T + bias, relu.  fp16 m16n8k16 mma.  CTA 256 thr,
// tile 128m x 128n, KT=64, 3-stage cp.async pipeline, 128B-row XOR swizzle,
// ldmatrix.x4 frags.  (R16 version, verbatim)
// ---------------------------------------------------------------------------
#define KT     64
#define NKT    (K2 / KT)        // 8
#define M_BLK  128
#define N_BLK  128

__global__ __launch_bounds__(256, 2)
void out_gemm_kernel(const float* __restrict__ bias,
                     float* __restrict__ out)
{
    __shared__ uint32_t sA[3][M_BLK * 32];   // 3 x 16KB
    __shared__ uint32_t sB[3][N_BLK * 32];   // 3 x 16KB

    const int tid  = threadIdx.x;
    const int warp = tid >> 5;
    const int lane = tid & 31;
    const int g    = lane >> 2;
    const int tig  = lane & 3;
    const int wm   = warp >> 1;
    const int wn   = warp & 1;
    const int m0   = blockIdx.x * M_BLK;
    const int lrow = lane & 15;
    const int lch  = lane >> 4;

    const __half* yp = g_ypow;

    float acc[2][8][4];
    #pragma unroll
    for (int a = 0; a < 2; ++a)
        #pragma unroll
        for (int b = 0; b < 8; ++b)
            #pragma unroll
            for (int c = 0; c < 4; ++c) acc[a][b][c] = 0.0f;

    auto stage = [&](int kt, int st) {
        #pragma unroll
        for (int i = 0; i < 4; ++i) {          // A: 1024 chunks
            int id = tid + i * 256;
            int row = id >> 3, c = id & 7;
            cp_async16(smem_u32(&sA[st][swz8(row, c)]),
                       yp + (size_t)(m0 + row) * K2 + kt * KT + c * 8);
        }
        #pragma unroll
        for (int i = 0; i < 4; ++i) {          // B: 1024 chunks
            int id = tid + i * 256;
            int row = id >> 3, c = id & 7;
            cp_async16(smem_u32(&sB[st][swz8(row, c)]),
                       g_W + (size_t)row * K2 + kt * KT + c * 8);
        }
        asm volatile("cp.async.commit_group;");
    };

    stage(0, 0);
    stage(1, 1);
    stage(2, 2);

    for (int kt = 0; kt < NKT; ++kt) {
        if (kt < NKT - 2)       asm volatile("cp.async.wait_group 2;");
        else if (kt == NKT - 2) asm volatile("cp.async.wait_group 1;");
        else                    asm volatile("cp.async.wait_group 0;");
        __syncthreads();
        const int st = kt % 3;

        #pragma unroll
        for (int ks = 0; ks < 4; ++ks) {
            const int ch = ks * 2 + lch;
            uint32_t a[2][4];
            #pragma unroll
            for (int mi = 0; mi < 2; ++mi) {
                int row = wm * 32 + mi * 16 + lrow;
                ldsm_x4(a[mi], smem_u32(&sA[st][swz8(row, ch)]));
            }
            uint32_t b[4][4];
            #pragma unroll
            for (int p = 0; p < 4; ++p) {
                int row = wn * 64 + p * 16 + lrow;
                ldsm_x4(b[p], smem_u32(&sB[st][swz8(row, ch)]));
            }
            #pragma unroll
            for (int p = 0; p < 4; ++p) {
                mma_f16(acc[0][2*p][0], acc[0][2*p][1], acc[0][2*p][2], acc[0][2*p][3],
                        a[0][0], a[0][1], a[0][2], a[0][3], b[p][0], b[p][2]);
                mma_f16(acc[0][2*p+1][0], acc[0][2*p+1][1], acc[0][2*p+1][2], acc[0][2*p+1][3],
                        a[0][0], a[0][1], a[0][2], a[0][3], b[p][1], b[p][3]);
                mma_f16(acc[1][2*p][0], acc[1][2*p][1], acc[1][2*p][2], acc[1][2*p][3],
                        a[1][0], a[1][1], a[1][2], a[1][3], b[p][0], b[p][2]);
                mma_f16(acc[1][2*p+1][0], acc[1][2*p+1][1], acc[1][2*p+1][2], acc[1][2*p+1][3],
                        a[1][0], a[1][1], a[1][2], a[1][3], b[p][1], b[p][3]);
            }
        }
        __syncthreads();
        if (kt + 3 < NKT) stage(kt + 3, st);
    }

    #pragma unroll
    for (int nt = 0; nt < 8; ++nt) {
        const int col = wn * 64 + nt * 8 + 2 * tig;
        const float b0 = __ldg(&bias[col]);
        const float b1 = __ldg(&bias[col + 1]);
        #pragma unroll
        for (int mi = 0; mi < 2; ++mi) {
            const int row = m0 + wm * 32 + mi * 16 + g;
            float2 v0, v1;
            v0.x = fmaxf(acc[mi][nt][0] + b0, 0.0f);
            v0.y = fmaxf(acc[mi][nt][1] + b1, 0.0f);
            v1.x = fmaxf(acc[mi][nt][2] + b0, 0.0f);
            v1.y = fmaxf(acc[mi][nt][3] + b1, 0.0f);
            *(float2*)(out + (size_t)row * COUT + col)       = v0;
            *(float2*)(out + (size_t)(row + 8) * COUT + col) = v1;
        }
    }
}

extern "C" void kernel_launch(void* const* d_in, const int* in_sizes, int n_in,
                              void* d_out, int out_size)
{
    const float* signal = (const float*)d_in[0];
    const int*   pidx   = (const int*)  d_in[1];
    const float* convk  = (const float*)d_in[2];
    const float* W      = (const float*)d_in[3];
    const float* bias   = (const float*)d_in[4];
    float* out = (float*)d_out;

    cvt_kernel<<<264, 256>>>(signal, W);
    ypow_kernel<<<BV / 2, 64>>>(pidx, convk);
    out_gemm_kernel<<<BV / M_BLK, 256>>>(bias, out);
}